// round 15
// baseline (speedup 1.0000x reference)
#include <cuda_runtime.h>
#include <cuda_bf16.h>
#include <cstdint>

// ---------------- problem constants ----------------
#define BB 4
#define CC 64
#define HH 192
#define WW 192
#define HWW (HH*WW)
#define DG 8
#define CG 8
#define PW 194
#define PIMG (PW*PW)
#define MROWS (BB*PIMG)
#define GUARD 512
#define ROWSA (GUARD + MROWS + 1024)
#define NTIL256 ((MROWS + 255)/256)

// ---------------- scratch ----------------
// All bf16 hi/lo activation buffers are stored ROW-SWIZZLED in gmem:
// row g (64 ch = 128B): channel c lives at elem ((c>>3) ^ (g&7))*8 + (c&7).
__device__ __align__(256) float g_xnbr[(size_t)ROWSA * 64];
__device__ __align__(256) float g_xfc [(size_t)ROWSA * 64];
__device__ __align__(256) float g_offb[(size_t)ROWSA * 216];
__device__ __align__(256) __nv_bfloat16 g_nbr_h[(size_t)ROWSA*64], g_nbr_l[(size_t)ROWSA*64];
__device__ __align__(256) __nv_bfloat16 g_ref_h[(size_t)ROWSA*64], g_ref_l[(size_t)ROWSA*64];
__device__ __align__(256) __nv_bfloat16 g_b1_h [(size_t)ROWSA*64], g_b1_l [(size_t)ROWSA*64];
__device__ __align__(256) __nv_bfloat16 g_b2_h [(size_t)ROWSA*64], g_b2_l [(size_t)ROWSA*64];
__device__ __align__(256) __nv_bfloat16 g_b3_h [(size_t)ROWSA*64], g_b3_l [(size_t)ROWSA*64];
__device__ __align__(256) __nv_bfloat16 g_b4_h [(size_t)ROWSA*64], g_b4_l [(size_t)ROWSA*64];
#define WOFF_OC1   0
#define WOFF_OC2   (WOFF_OC1 + 9*2*64*64)
#define WOFF_D1OFF (WOFF_OC2 + 9*1*64*64)
#define WOFF_FC    (WOFF_D1OFF + 9*1*216*64)
#define WOFF_CAS1  (WOFF_FC + 9*1*64*64)
#define WOFF_CAS2  (WOFF_CAS1 + 9*2*64*64)
#define WOFF_CDOFF (WOFF_CAS2 + 9*1*64*64)
#define WOFF_DCN1  (WOFF_CDOFF + 9*1*216*64)
#define WOFF_CASD  (WOFF_DCN1 + 9*1*64*64)
#define WTOT       (WOFF_CASD + 9*1*64*64)
__device__ __align__(256) __nv_bfloat16 g_w_h[WTOT], g_w_l[WTOT];   // pre-swizzled weight image

// ---------------- PTX helpers (baseline ISA, compute_103-legal) ----------------
__device__ __forceinline__ uint32_t smem_u32(const void* p) {
    uint32_t a;
    asm("{ .reg .u64 t; cvta.to.shared.u64 t, %1; cvt.u32.u64 %0, t; }" : "=r"(a) : "l"(p));
    return a;
}
__device__ __forceinline__ void ldsm_x4(uint32_t* r, uint32_t a) {
    asm volatile("ldmatrix.sync.aligned.m8n8.x4.shared.b16 {%0,%1,%2,%3}, [%4];"
        : "=r"(r[0]), "=r"(r[1]), "=r"(r[2]), "=r"(r[3]) : "r"(a));
}
__device__ __forceinline__ void ldsm_x2(uint32_t* r, uint32_t a) {
    asm volatile("ldmatrix.sync.aligned.m8n8.x2.shared.b16 {%0,%1}, [%2];"
        : "=r"(r[0]), "=r"(r[1]) : "r"(a));
}
__device__ __forceinline__ void mma_bf16(float* c, const uint32_t* a, const uint32_t* b) {
    asm volatile(
        "mma.sync.aligned.m16n8k16.row.col.f32.bf16.bf16.f32 "
        "{%0,%1,%2,%3}, {%4,%5,%6,%7}, {%8,%9}, {%0,%1,%2,%3};"
        : "+f"(c[0]), "+f"(c[1]), "+f"(c[2]), "+f"(c[3])
        : "r"(a[0]), "r"(a[1]), "r"(a[2]), "r"(a[3]), "r"(b[0]), "r"(b[1]));
}
__device__ __forceinline__ void mbar_init(uint32_t mbar, uint32_t cnt) {
    asm volatile("mbarrier.init.shared.b64 [%0], %1;" :: "r"(mbar), "r"(cnt) : "memory");
}
__device__ __forceinline__ void mbar_expect_tx(uint32_t mbar, uint32_t bytes) {
    asm volatile("mbarrier.arrive.expect_tx.shared.b64 _, [%0], %1;" :: "r"(mbar), "r"(bytes) : "memory");
}
__device__ __forceinline__ void bulk_g2s(uint32_t dst, const void* src, uint32_t bytes, uint32_t mbar) {
    asm volatile("cp.async.bulk.shared::cta.global.mbarrier::complete_tx::bytes [%0], [%1], %2, [%3];"
        :: "r"(dst), "l"(src), "r"(bytes), "r"(mbar) : "memory");
}
__device__ __forceinline__ void mbar_wait(uint32_t mbar, uint32_t parity) {
    uint32_t done;
    asm volatile(
        "{\n\t.reg .pred p;\n\t"
        "mbarrier.try_wait.parity.acquire.cta.shared::cta.b64 p, [%1], %2;\n\t"
        "selp.b32 %0, 1, 0, p;\n\t}"
        : "=r"(done) : "r"(mbar), "r"(parity) : "memory");
    if (!done) {
        asm volatile(
            "{\n\t.reg .pred P1;\n\t"
            "WAIT_LOOP_%=:\n\t"
            "mbarrier.try_wait.parity.acquire.cta.shared::cta.b64 P1, [%0], %1, 0x989680;\n\t"
            "@P1 bra.uni WAIT_DONE_%=;\n\t"
            "bra.uni WAIT_LOOP_%=;\n\t"
            "WAIT_DONE_%=:\n\t}"
            :: "r"(mbar), "r"(parity) : "memory");
    }
}
__device__ __forceinline__ void prefetch_l2(const void* p) {
    asm volatile("prefetch.global.L2 [%0];" :: "l"(p));
}
// swizzled element index within a 64-ch row, key = row&7
__device__ __forceinline__ int swz_elem(int c, int key) {
    return (((c >> 3) ^ key) << 3) + (c & 7);
}

// ---------------- input conversion (writes SWIZZLED bf16 rows) ----------------
template<bool F32OUT>
__global__ void convert_in_kernel(const float* __restrict__ in, float* __restrict__ outF,
                                  __nv_bfloat16* __restrict__ hi, __nv_bfloat16* __restrict__ lo)
{
    int p = blockIdx.x * blockDim.x + threadIdx.x;
    if (p >= BB * HWW) return;
    int x = p % WW; int t = p / WW; int y = t % HH; int b = t / HH;
    size_t g = (size_t)GUARD + (size_t)b * PIMG + (size_t)(y + 1) * PW + (x + 1);
    const int key = (int)(g & 7);
#pragma unroll
    for (int c = 0; c < 64; ++c) {
        float v = in[((size_t)(b * 64 + c)) * HWW + (size_t)y * WW + x];
        if (F32OUT) outF[g * 64 + c] = v;
        __nv_bfloat16 h = __float2bfloat16(v);
        int sc = swz_elem(c, key);
        hi[g * 64 + sc] = h;
        lo[g * 64 + sc] = __float2bfloat16(v - __bfloat162float(h));
    }
}

// ---------------- fused weight prep (pre-swizzled image) ----------------
struct WPrepArgs {
    const float* src[10];
    int O[10];
    int Cin[10];
    long woff[10];
};
__global__ void weight_prep_all_kernel(WPrepArgs a,
                                       __nv_bfloat16* __restrict__ whi,
                                       __nv_bfloat16* __restrict__ wlo)
{
    const int ci = blockIdx.y;
    const int O = a.O[ci], Cin = a.Cin[ci];
    const int n = O * Cin * 9;
    const float* __restrict__ w = a.src[ci];
    const long woff = a.woff[ci];
    for (int idx = blockIdx.x * blockDim.x + threadIdx.x; idx < n;
         idx += gridDim.x * blockDim.x) {
        int tap = idx % 9; int t = idx / 9; int cin = t % Cin; int o = t / Cin;
        float v = w[idx];
        int seg = cin >> 6, k = cin & 63;
        size_t blockb = (size_t)woff + (((size_t)tap * (Cin >> 6) + seg) * O) * 64;
        size_t dst = blockb + (size_t)o * 64 + (size_t)swz_elem(k, o & 7);
        __nv_bfloat16 h = __float2bfloat16(v);
        whi[dst] = h;
        wlo[dst] = __float2bfloat16(v - __bfloat162float(h));
    }
}

// ---------------- conv: all staging via cp.async.bulk + L2 prefetch of next A ----------------
template<int NT, int NTOT, int SEGS, bool EPI_F32, bool EPI_BF16, bool LRELU>
__global__ __launch_bounds__(256, 2)
void conv_mma_kernel(const __nv_bfloat16* __restrict__ Ahi0, const __nv_bfloat16* __restrict__ Alo0,
                     const __nv_bfloat16* __restrict__ Ahi1, const __nv_bfloat16* __restrict__ Alo1,
                     const __nv_bfloat16* __restrict__ Whi, const __nv_bfloat16* __restrict__ Wlo,
                     const float* __restrict__ bias,
                     float* __restrict__ outF,
                     __nv_bfloat16* __restrict__ outHi, __nv_bfloat16* __restrict__ outLo)
{
    extern __shared__ __align__(1024) char smem[];
    constexpr int AROWS = 258;
    constexpr int ABUF  = AROWS * 128;
    constexpr int BBUF  = NT * 128;
    constexpr int OFF_A = 1024;
    constexpr int OFF_B = OFF_A + 2 * ABUF;
    constexpr int NB  = NT / 8;
    constexpr int NBP = NB / 2;
    constexpr bool NBODD = (NB & 1) != 0;
    constexpr int NSS = 3 * SEGS;
    constexpr int NST = 9 * SEGS;

    float* sBias = (float*)smem;                 // [0, 512)
    const uint32_t sb = smem_u32(smem);
    const uint32_t mb0 = sb + 512;
    const uint32_t mb1 = sb + 520;
    const uint32_t mbA = sb + 528;

    const int tid  = threadIdx.x;
    const int lane = tid & 31;
    const int warp = tid >> 5;
    const int ocb  = blockIdx.y;
    const long m0  = (long)blockIdx.x * 256;

    for (int i = tid; i < NT; i += 256) sBias[i] = bias[ocb * NT + i];

    float acc[2][NB][4];
#pragma unroll
    for (int mt = 0; mt < 2; ++mt)
#pragma unroll
        for (int nb = 0; nb < NB; ++nb)
#pragma unroll
            for (int j = 0; j < 4; ++j) acc[mt][nb][j] = 0.f;

    const int l7 = lane & 7;
    const uint32_t aRow = (uint32_t)(warp * 32 + ((lane >> 3) & 1) * 8 + l7);
    const int aU = (lane >> 4) & 1;
    const int bKh = (lane >> 3) & 1;
    const int bNs = (lane >> 4) & 1;

    auto panel_src = [&](int ss, const __nv_bfloat16*& ah, const __nv_bfloat16*& al, long& base) {
        const int dy  = ss / SEGS;
        const int seg = ss % SEGS;
        ah = (seg == 0) ? Ahi0 : Ahi1;
        al = (seg == 0) ? Alo0 : Alo1;
        base = (long)GUARD + m0 + (long)(dy - 1) * PW - 1;
    };
    auto bulk_A = [&](int ss) {
        const __nv_bfloat16 *ah, *al; long base;
        panel_src(ss, ah, al, base);
        mbar_expect_tx(mbA, 2 * ABUF);
        bulk_g2s(sb + OFF_A,        ah + (size_t)base * 64, ABUF, mbA);
        bulk_g2s(sb + OFF_A + ABUF, al + (size_t)base * 64, ABUF, mbA);
    };
    auto prefetch_A = [&](int ss) {
        const __nv_bfloat16 *ah, *al; long base;
        panel_src(ss, ah, al, base);
        // 258 rows * 128B = 258 lines per panel; 2 panels -> ~2-3 lines/thread
        for (int r = tid; r < AROWS; r += 256) {
            prefetch_l2(ah + (size_t)(base + r) * 64);
            prefetch_l2(al + (size_t)(base + r) * 64);
        }
    };
    auto bulk_B = [&](int s) {
        const int ss = s / 3, dxi = s % 3;
        const int dy = ss / SEGS, seg = ss % SEGS;
        const int tap = dy * 3 + dxi;
        const size_t wbase = (((size_t)tap * SEGS + seg) * NTOT + (size_t)ocb * NT) * 64;
        const uint32_t mb = (s & 1) ? mb1 : mb0;
        const uint32_t dBH = sb + OFF_B + (s & 1) * 2 * BBUF;
        mbar_expect_tx(mb, 2 * BBUF);
        bulk_g2s(dBH,        Whi + wbase, BBUF, mb);
        bulk_g2s(dBH + BBUF, Wlo + wbase, BBUF, mb);
    };

    if (tid == 0) { mbar_init(mb0, 1); mbar_init(mb1, 1); mbar_init(mbA, 1); }
    __syncthreads();
    if (tid == 0) { bulk_A(0); bulk_B(0); }

    for (int s = 0; s < NST; ++s) {
        const int ss = s / 3, dxi = s % 3;

        if (dxi == 0) mbar_wait(mbA, ss & 1);            // A panel for this superstage
        mbar_wait((s & 1) ? mb1 : mb0, (s >> 1) & 1);    // B(s)
        __syncthreads();                                 // all warps past compute(s-1)

        if (tid == 0 && s + 1 < NST) bulk_B(s + 1);
        if (dxi == 0 && ss + 1 < NSS) prefetch_A(ss + 1);  // warm L2 for next panel

        const int dy = ss / SEGS;
        const int bm = (int)(((dy - 1) * PW - 1) & 7);   // (base&7); m0,GUARD ≡ 0 mod 8
        const uint32_t aH = sb + OFF_A;
        const uint32_t aL = aH + ABUF;
        const uint32_t bH = sb + OFF_B + (s & 1) * 2 * BBUF;
        const uint32_t bL = bH + BBUF;
        const uint32_t krow = (uint32_t)((l7 + dxi + bm) & 7);

#pragma unroll
        for (int c = 0; c < 4; ++c) {
            uint32_t ahf[2][4], alf[2][4];
#pragma unroll
            for (int mt = 0; mt < 2; ++mt) {
                uint32_t row = aRow + mt * 16 + dxi;
                uint32_t off = row * 128 + ((uint32_t)((2 * c + aU)) ^ krow) * 16;
                ldsm_x4(ahf[mt], aH + off);
                ldsm_x4(alf[mt], aL + off);
            }
#pragma unroll
            for (int nbp = 0; nbp < NBP; ++nbp) {
                uint32_t row = (uint32_t)((nbp * 2 + bNs) * 8 + l7);
                uint32_t offb = row * 128 + ((uint32_t)((2 * c + bKh) ^ l7)) * 16;
                uint32_t bh[4], bl[4];
                ldsm_x4(bh, bH + offb);
                ldsm_x4(bl, bL + offb);
#pragma unroll
                for (int half = 0; half < 2; ++half) {
                    const int nb = nbp * 2 + half;
                    mma_bf16(acc[0][nb], ahf[0], bh + 2 * half);
                    mma_bf16(acc[1][nb], ahf[1], bh + 2 * half);
                    mma_bf16(acc[0][nb], ahf[0], bl + 2 * half);
                    mma_bf16(acc[1][nb], ahf[1], bl + 2 * half);
                    mma_bf16(acc[0][nb], alf[0], bh + 2 * half);
                    mma_bf16(acc[1][nb], alf[1], bh + 2 * half);
                }
            }
            if (NBODD) {
                const int nb = NB - 1;
                uint32_t row = (uint32_t)(nb * 8 + l7);
                uint32_t offb = row * 128 + ((uint32_t)((2 * c + bKh) ^ l7)) * 16;
                uint32_t bh[2], bl[2];
                ldsm_x2(bh, bH + offb);
                ldsm_x2(bl, bL + offb);
                mma_bf16(acc[0][nb], ahf[0], bh);
                mma_bf16(acc[1][nb], ahf[1], bh);
                mma_bf16(acc[0][nb], ahf[0], bl);
                mma_bf16(acc[1][nb], ahf[1], bl);
                mma_bf16(acc[0][nb], alf[0], bh);
                mma_bf16(acc[1][nb], alf[1], bh);
            }
        }

        if (dxi == 2 && ss + 1 < NSS) {
            __syncthreads();          // all warps done reading A(ss)
            if (tid == 0) bulk_A(ss + 1);
        }
    }

    // ---- epilogue (bf16 outputs written SWIZZLED) ----
    const long gbase = m0 + warp * 32;
    const int ncol0 = 2 * (lane & 3);
#pragma unroll
    for (int mt = 0; mt < 2; ++mt) {
#pragma unroll
        for (int half = 0; half < 2; ++half) {
            long g = gbase + mt * 16 + (lane >> 2) + half * 8;
            bool valid = (g < MROWS);
            if (valid) {
                long q = g % PIMG;
                int py = (int)(q / PW), px = (int)(q % PW);
                valid = (py >= 1) && (py < PW - 1) && (px >= 1) && (px < PW - 1);
            }
            if (!valid) continue;
            const size_t orow = (size_t)(GUARD + g);
            const int okey = (int)(orow & 7);
#pragma unroll
            for (int nb = 0; nb < NB; ++nb) {
                float v0 = acc[mt][nb][half * 2 + 0] + sBias[nb * 8 + ncol0];
                float v1 = acc[mt][nb][half * 2 + 1] + sBias[nb * 8 + ncol0 + 1];
                if (LRELU) {
                    v0 = (v0 >= 0.f) ? v0 : 0.1f * v0;
                    v1 = (v1 >= 0.f) ? v1 : 0.1f * v1;
                }
                const int col = ocb * NT + nb * 8 + ncol0;
                if (EPI_F32) {
                    outF[orow * NTOT + col]     = v0;
                    outF[orow * NTOT + col + 1] = v1;
                }
                if (EPI_BF16) {
                    int sc = swz_elem(col, okey);
                    __nv_bfloat16 h0 = __float2bfloat16(v0);
                    __nv_bfloat16 h1 = __float2bfloat16(v1);
                    outHi[orow * NTOT + sc]     = h0;
                    outHi[orow * NTOT + sc + 1] = h1;
                    outLo[orow * NTOT + sc]     = __float2bfloat16(v0 - __bfloat162float(h0));
                    outLo[orow * NTOT + sc + 1] = __float2bfloat16(v1 - __bfloat162float(h1));
                }
            }
        }
    }
}

// ---------------- DCNv2 via MMA: M=256 (1 thread samples 1 pixel x 8 dg) ----------------
template<bool LRELU, bool NCHW_OUT>
__global__ __launch_bounds__(256, 2)
void dcn_mma_kernel(const float* __restrict__ xf,
                    const float* __restrict__ off,
                    const __nv_bfloat16* __restrict__ Whi, const __nv_bfloat16* __restrict__ Wlo,
                    const float* __restrict__ bias,
                    float* __restrict__ outF,
                    __nv_bfloat16* __restrict__ outHi, __nv_bfloat16* __restrict__ outLo)
{
    extern __shared__ __align__(1024) char smem[];
    constexpr int ABUF  = 256 * 128;
    constexpr int BBUF  = 64 * 128;
    constexpr int OFF_A = 1024;
    constexpr int OFF_B = OFF_A + 2 * ABUF;

    float* sBias = (float*)smem;
    const uint32_t sb = smem_u32(smem);
    const uint32_t mb0 = sb + 512;
    const uint32_t mb1 = sb + 520;

    const int tid  = threadIdx.x;
    const int lane = tid & 31;
    const int warp = tid >> 5;
    const long m0  = (long)blockIdx.x * 256;

    if (tid < 64) sBias[tid] = bias[tid];

    const int p   = tid;                      // one pixel per thread
    const long g  = m0 + p;
    const long gcl = (g < MROWS) ? g : 0;
    const int b   = (int)(gcl / PIMG);
    const long q  = gcl % PIMG;
    const int gy  = (int)(q / PW) - 1;
    const int gx  = (int)(q % PW) - 1;
    const size_t prow = (size_t)GUARD + gcl;
    const float* offP = off + prow * 216;
    const float* xfb  = xf + ((size_t)GUARD + (size_t)b * PIMG) * 64;

    float acc[2][8][4];
#pragma unroll
    for (int mt = 0; mt < 2; ++mt)
#pragma unroll
        for (int nb = 0; nb < 8; ++nb)
#pragma unroll
            for (int j = 0; j < 4; ++j) acc[mt][nb][j] = 0.f;

    const int l7 = lane & 7;
    const uint32_t aRow = (uint32_t)(warp * 32 + ((lane >> 3) & 1) * 8 + l7);
    const int aU = (lane >> 4) & 1;
    const int bKh = (lane >> 3) & 1;
    const int bNs = (lane >> 4) & 1;

    auto bulk_B = [&](int s) {
        const size_t wbase = (size_t)s * 64 * 64;
        const uint32_t mb = (s & 1) ? mb1 : mb0;
        const uint32_t dBH = sb + OFF_B + (s & 1) * 2 * BBUF;
        mbar_expect_tx(mb, 2 * BBUF);
        bulk_g2s(dBH,        Whi + wbase, BBUF, mb);
        bulk_g2s(dBH + BBUF, Wlo + wbase, BBUF, mb);
    };

    if (tid == 0) { mbar_init(mb0, 1); mbar_init(mb1, 1); }
    __syncthreads();
    if (tid == 0) bulk_B(0);

    for (int s = 0; s < 9; ++s) {
        __syncthreads();                 // prior stage's A/B reads complete
        if (tid == 0 && s + 1 < 9) bulk_B(s + 1);

        const int ky = s / 3, kx = s % 3;
        const uint32_t arow_sw = (uint32_t)p * 128;
        const uint32_t asx = ((uint32_t)p & 7) * 16;
#pragma unroll
        for (int dg = 0; dg < 8; ++dg) {
            float dy = offP[dg * 18 + 2 * s + 0];
            float dx = offP[dg * 18 + 2 * s + 1];
            float ml = offP[144 + dg * 9 + s];
            float m  = 1.f / (1.f + __expf(-ml));

            float py = (float)gy - 1.f + (float)ky + dy;
            float px = (float)gx - 1.f + (float)kx + dx;
            float y0f = floorf(py), x0f = floorf(px);
            float wy = py - y0f, wx = px - x0f;
            int y0 = (int)y0f, x0 = (int)x0f;

            float cw00 = (1.f - wy) * (1.f - wx);
            float cw01 = (1.f - wy) * wx;
            float cw10 = wy * (1.f - wx);
            float cw11 = wy * wx;

            float sv[8];
#pragma unroll
            for (int i = 0; i < 8; ++i) sv[i] = 0.f;
#pragma unroll
            for (int cy = 0; cy < 2; ++cy) {
#pragma unroll
                for (int cx = 0; cx < 2; ++cx) {
                    int yy = y0 + cy, xx = x0 + cx;
                    float cwv = (cy == 0) ? ((cx == 0) ? cw00 : cw01)
                                          : ((cx == 0) ? cw10 : cw11);
                    if (yy >= 0 && yy < HH && xx >= 0 && xx < WW) {
                        const float4* ptr = reinterpret_cast<const float4*>(
                            xfb + ((size_t)(yy + 1) * PW + (xx + 1)) * 64 + dg * 8);
                        float4 a = __ldg(&ptr[0]);
                        float4 c = __ldg(&ptr[1]);
                        sv[0] += cwv * a.x; sv[1] += cwv * a.y;
                        sv[2] += cwv * a.z; sv[3] += cwv * a.w;
                        sv[4] += cwv * c.x; sv[5] += cwv * c.y;
                        sv[6] += cwv * c.z; sv[7] += cwv * c.w;
                    }
                }
            }
            uint32_t hp[4], lp[4];
#pragma unroll
            for (int i = 0; i < 4; ++i) {
                float v0 = sv[2 * i] * m, v1 = sv[2 * i + 1] * m;
                __nv_bfloat16 h0 = __float2bfloat16(v0);
                __nv_bfloat16 h1 = __float2bfloat16(v1);
                __nv_bfloat16 e0 = __float2bfloat16(v0 - __bfloat162float(h0));
                __nv_bfloat16 e1 = __float2bfloat16(v1 - __bfloat162float(h1));
                hp[i] = ((uint32_t)*(uint16_t*)&h1 << 16) | (uint32_t)*(uint16_t*)&h0;
                lp[i] = ((uint32_t)*(uint16_t*)&e1 << 16) | (uint32_t)*(uint16_t*)&e0;
            }
            uint32_t o = arow_sw + (((uint32_t)dg * 16) ^ asx);
            *(uint4*)(smem + OFF_A + o)        = make_uint4(hp[0], hp[1], hp[2], hp[3]);
            *(uint4*)(smem + OFF_A + ABUF + o) = make_uint4(lp[0], lp[1], lp[2], lp[3]);
        }

        mbar_wait((s & 1) ? mb1 : mb0, (s >> 1) & 1);
        __syncthreads();                               // A stores + B(s) visible

        const uint32_t aH = sb + OFF_A;
        const uint32_t aL = aH + ABUF;
        const uint32_t bH = sb + OFF_B + (s & 1) * 2 * BBUF;
        const uint32_t bL = bH + BBUF;

#pragma unroll
        for (int c = 0; c < 4; ++c) {
            uint32_t ahf[2][4], alf[2][4];
#pragma unroll
            for (int mt = 0; mt < 2; ++mt) {
                uint32_t row = aRow + mt * 16;
                uint32_t offA = row * 128 + ((uint32_t)((2 * c + aU) ^ l7)) * 16;
                ldsm_x4(ahf[mt], aH + offA);
                ldsm_x4(alf[mt], aL + offA);
            }
#pragma unroll
            for (int nbp = 0; nbp < 4; ++nbp) {
                uint32_t row = (uint32_t)((nbp * 2 + bNs) * 8 + l7);
                uint32_t offb2 = row * 128 + ((uint32_t)((2 * c + bKh) ^ l7)) * 16;
                uint32_t bh[4], bl[4];
                ldsm_x4(bh, bH + offb2);
                ldsm_x4(bl, bL + offb2);
#pragma unroll
                for (int half = 0; half < 2; ++half) {
                    const int nb = nbp * 2 + half;
                    mma_bf16(acc[0][nb], ahf[0], bh + 2 * half);
                    mma_bf16(acc[1][nb], ahf[1], bh + 2 * half);
                    mma_bf16(acc[0][nb], ahf[0], bl + 2 * half);
                    mma_bf16(acc[1][nb], ahf[1], bl + 2 * half);
                    mma_bf16(acc[0][nb], alf[0], bh + 2 * half);
                    mma_bf16(acc[1][nb], alf[1], bh + 2 * half);
                }
            }
        }
    }

    const long gbase = m0 + warp * 32;
    const int ncol0 = 2 * (lane & 3);
#pragma unroll
    for (int mt = 0; mt < 2; ++mt) {
#pragma unroll
        for (int half = 0; half < 2; ++half) {
            long g2 = gbase + mt * 16 + (lane >> 2) + half * 8;
            bool valid = (g2 < MROWS);
            int b2 = 0, gy2 = 0, gx2 = 0;
            if (valid) {
                b2 = (int)(g2 / PIMG);
                long q2 = g2 % PIMG;
                gy2 = (int)(q2 / PW) - 1;
                gx2 = (int)(q2 % PW) - 1;
                valid = (gy2 >= 0) && (gy2 < HH) && (gx2 >= 0) && (gx2 < WW);
            }
            if (!valid) continue;
            const size_t orow = (size_t)(GUARD + g2);
            const int okey = (int)(orow & 7);
#pragma unroll
            for (int nb = 0; nb < 8; ++nb) {
#pragma unroll
                for (int j = 0; j < 2; ++j) {
                    const int oc = nb * 8 + ncol0 + j;
                    float v = acc[mt][nb][half * 2 + j] + sBias[oc];
                    if (LRELU) v = (v >= 0.f) ? v : 0.1f * v;
                    if (NCHW_OUT) {
                        outF[((size_t)(b2 * CC + oc)) * HWW + (size_t)gy2 * WW + gx2] = v;
                    } else {
                        int sc = swz_elem(oc, okey);
                        __nv_bfloat16 h = __float2bfloat16(v);
                        outHi[orow * 64 + sc] = h;
                        outLo[orow * 64 + sc] = __float2bfloat16(v - __bfloat162float(h));
                    }
                }
            }
        }
    }
}

// ---------------- launch ----------------
extern "C" void kernel_launch(void* const* d_in, const int* in_sizes, int n_in,
                              void* d_out, int out_size)
{
    const float* nbr     = (const float*)d_in[0];
    const float* ref     = (const float*)d_in[1];
    const float* oc1_w   = (const float*)d_in[2];
    const float* oc1_b   = (const float*)d_in[3];
    const float* oc2_w   = (const float*)d_in[4];
    const float* oc2_b   = (const float*)d_in[5];
    const float* d1off_w = (const float*)d_in[6];
    const float* d1off_b = (const float*)d_in[7];
    const float* dcn1_w  = (const float*)d_in[8];
    const float* dcn1_b  = (const float*)d_in[9];
    const float* fc_w    = (const float*)d_in[10];
    const float* fc_b    = (const float*)d_in[11];
    const float* cas1_w  = (const float*)d_in[12];
    const float* cas1_b  = (const float*)d_in[13];
    const float* cas2_w  = (const float*)d_in[14];
    const float* cas2_b  = (const float*)d_in[15];
    const float* cdoff_w = (const float*)d_in[16];
    const float* cdoff_b = (const float*)d_in[17];
    const float* casd_w  = (const float*)d_in[18];
    const float* casd_b  = (const float*)d_in[19];
    float* outp = (float*)d_out;

    float *xnbr, *xfc, *offb;
    __nv_bfloat16 *nh, *nl, *rh, *rl, *b1h, *b1l, *b2h, *b2l, *b3h, *b3l, *b4h, *b4l, *wh, *wl;
    cudaGetSymbolAddress((void**)&xnbr, g_xnbr);
    cudaGetSymbolAddress((void**)&xfc,  g_xfc);
    cudaGetSymbolAddress((void**)&offb, g_offb);
    cudaGetSymbolAddress((void**)&nh,  g_nbr_h); cudaGetSymbolAddress((void**)&nl, g_nbr_l);
    cudaGetSymbolAddress((void**)&rh,  g_ref_h); cudaGetSymbolAddress((void**)&rl, g_ref_l);
    cudaGetSymbolAddress((void**)&b1h, g_b1_h);  cudaGetSymbolAddress((void**)&b1l, g_b1_l);
    cudaGetSymbolAddress((void**)&b2h, g_b2_h);  cudaGetSymbolAddress((void**)&b2l, g_b2_l);
    cudaGetSymbolAddress((void**)&b3h, g_b3_h);  cudaGetSymbolAddress((void**)&b3l, g_b3_l);
    cudaGetSymbolAddress((void**)&b4h, g_b4_h);  cudaGetSymbolAddress((void**)&b4l, g_b4_l);
    cudaGetSymbolAddress((void**)&wh,  g_w_h);   cudaGetSymbolAddress((void**)&wl,  g_w_l);

    auto C64S2 = conv_mma_kernel<64, 64, 2, false, true,  true >;
    auto C64S1 = conv_mma_kernel<64, 64, 1, false, true,  true >;
    auto C216  = conv_mma_kernel<72, 216, 1, true,  false, false>;
    auto CFC   = conv_mma_kernel<64, 64, 1, true,  true,  false>;
    auto DCN1  = dcn_mma_kernel<false, false>;
    auto DCNC  = dcn_mma_kernel<true,  true >;

    const int smem64 = 1024 + 2 * (258 * 128) + 4 * 64 * 128;   // 99840
    const int smem72 = 1024 + 2 * (258 * 128) + 4 * 72 * 128;   // 103936
    const int smemD  = 1024 + 2 * (256 * 128) + 4 * 64 * 128;   // 99328
    cudaFuncSetAttribute(C64S2, cudaFuncAttributeMaxDynamicSharedMemorySize, smem64);
    cudaFuncSetAttribute(C64S1, cudaFuncAttributeMaxDynamicSharedMemorySize, smem64);
    cudaFuncSetAttribute(CFC,   cudaFuncAttributeMaxDynamicSharedMemorySize, smem64);
    cudaFuncSetAttribute(C216,  cudaFuncAttributeMaxDynamicSharedMemorySize, smem72);
    cudaFuncSetAttribute(DCN1,  cudaFuncAttributeMaxDynamicSharedMemorySize, smemD);
    cudaFuncSetAttribute(DCNC,  cudaFuncAttributeMaxDynamicSharedMemorySize, smemD);

    const int cvtGrid = (BB * HWW + 255) / 256;
    dim3 g64(NTIL256, 1), g216(NTIL256, 3);

    convert_in_kernel<true ><<<cvtGrid, 256>>>(nbr, xnbr, nh, nl);
    convert_in_kernel<false><<<cvtGrid, 256>>>(ref, nullptr, rh, rl);
    {
        WPrepArgs a;
        a.src[0] = oc1_w;   a.O[0] = 64;  a.Cin[0] = 128; a.woff[0] = WOFF_OC1;
        a.src[1] = oc2_w;   a.O[1] = 64;  a.Cin[1] = 64;  a.woff[1] = WOFF_OC2;
        a.src[2] = d1off_w; a.O[2] = 216; a.Cin[2] = 64;  a.woff[2] = WOFF_D1OFF;
        a.src[3] = fc_w;    a.O[3] = 64;  a.Cin[3] = 64;  a.woff[3] = WOFF_FC;
        a.src[4] = cas1_w;  a.O[4] = 64;  a.Cin[4] = 128; a.woff[4] = WOFF_CAS1;
        a.src[5] = cas2_w;  a.O[5] = 64;  a.Cin[5] = 64;  a.woff[5] = WOFF_CAS2;
        a.src[6] = cdoff_w; a.O[6] = 216; a.Cin[6] = 64;  a.woff[6] = WOFF_CDOFF;
        a.src[7] = dcn1_w;  a.O[7] = 64;  a.Cin[7] = 64;  a.woff[7] = WOFF_DCN1;
        a.src[8] = casd_w;  a.O[8] = 64;  a.Cin[8] = 64;  a.woff[8] = WOFF_CASD;
        a.src[9] = casd_w;  a.O[9] = 0;   a.Cin[9] = 64;  a.woff[9] = WOFF_CASD;
        dim3 gW(64, 10);
        weight_prep_all_kernel<<<gW, 256>>>(a, wh, wl);
    }

    C64S2<<<g64, 256, smem64>>>(nh, nl, rh, rl, wh + WOFF_OC1, wl + WOFF_OC1, oc1_b, nullptr, b1h, b1l);
    C64S1<<<g64, 256, smem64>>>(b1h, b1l, nullptr, nullptr, wh + WOFF_OC2, wl + WOFF_OC2, oc2_b, nullptr, b2h, b2l);
    C216<<<g216, 256, smem72>>>(b2h, b2l, nullptr, nullptr, wh + WOFF_D1OFF, wl + WOFF_D1OFF, d1off_b, offb, nullptr, nullptr);
    DCN1<<<NTIL256, 256, smemD>>>(xnbr, offb, wh + WOFF_DCN1, wl + WOFF_DCN1, dcn1_b, nullptr, b3h, b3l);
    CFC<<<g64, 256, smem64>>>(b3h, b3l, nullptr, nullptr, wh + WOFF_FC, wl + WOFF_FC, fc_b, xfc, b4h, b4l);
    C64S2<<<g64, 256, smem64>>>(b4h, b4l, rh, rl, wh + WOFF_CAS1, wl + WOFF_CAS1, cas1_b, nullptr, b1h, b1l);
    C64S1<<<g64, 256, smem64>>>(b1h, b1l, nullptr, nullptr, wh + WOFF_CAS2, wl + WOFF_CAS2, cas2_b, nullptr, b2h, b2l);
    C216<<<g216, 256, smem72>>>(b2h, b2l, nullptr, nullptr, wh + WOFF_CDOFF, wl + WOFF_CDOFF, cdoff_b, offb, nullptr, nullptr);
    DCNC<<<NTIL256, 256, smemD>>>(xfc, offb, wh + WOFF_CASD, wl + WOFF_CASD, casd_b, outp, nullptr, nullptr);

    (void)in_sizes; (void)n_in; (void)out_size;
}

// round 16
// speedup vs baseline: 1.0324x; 1.0324x over previous
#include <cuda_runtime.h>
#include <cuda_bf16.h>
#include <cstdint>

// ---------------- problem constants ----------------
#define BB 4
#define CC 64
#define HH 192
#define WW 192
#define HWW (HH*WW)
#define DG 8
#define CG 8
#define PW 194
#define PIMG (PW*PW)
#define MROWS (BB*PIMG)
#define GUARD 512
#define ROWSA (GUARD + MROWS + 1024)
#define NTIL256 ((MROWS + 255)/256)
#define NTIL128 ((MROWS + 127)/128)

// ---------------- scratch ----------------
// All bf16 hi/lo activation buffers are stored ROW-SWIZZLED in gmem:
// row g (64 ch = 128B): channel c lives at elem ((c>>3) ^ (g&7))*8 + (c&7).
__device__ __align__(256) float g_xnbr[(size_t)ROWSA * 64];
__device__ __align__(256) float g_xfc [(size_t)ROWSA * 64];
__device__ __align__(256) float g_offb[(size_t)ROWSA * 216];
__device__ __align__(256) __nv_bfloat16 g_nbr_h[(size_t)ROWSA*64], g_nbr_l[(size_t)ROWSA*64];
__device__ __align__(256) __nv_bfloat16 g_ref_h[(size_t)ROWSA*64], g_ref_l[(size_t)ROWSA*64];
__device__ __align__(256) __nv_bfloat16 g_b1_h [(size_t)ROWSA*64], g_b1_l [(size_t)ROWSA*64];
__device__ __align__(256) __nv_bfloat16 g_b2_h [(size_t)ROWSA*64], g_b2_l [(size_t)ROWSA*64];
__device__ __align__(256) __nv_bfloat16 g_b3_h [(size_t)ROWSA*64], g_b3_l [(size_t)ROWSA*64];
__device__ __align__(256) __nv_bfloat16 g_b4_h [(size_t)ROWSA*64], g_b4_l [(size_t)ROWSA*64];
#define WOFF_OC1   0
#define WOFF_OC2   (WOFF_OC1 + 9*2*64*64)
#define WOFF_D1OFF (WOFF_OC2 + 9*1*64*64)
#define WOFF_FC    (WOFF_D1OFF + 9*1*216*64)
#define WOFF_CAS1  (WOFF_FC + 9*1*64*64)
#define WOFF_CAS2  (WOFF_CAS1 + 9*2*64*64)
#define WOFF_CDOFF (WOFF_CAS2 + 9*1*64*64)
#define WOFF_DCN1  (WOFF_CDOFF + 9*1*216*64)
#define WOFF_CASD  (WOFF_DCN1 + 9*1*64*64)
#define WTOT       (WOFF_CASD + 9*1*64*64)
__device__ __align__(256) __nv_bfloat16 g_w_h[WTOT], g_w_l[WTOT];   // pre-swizzled weight image

// ---------------- PTX helpers (baseline ISA, compute_103-legal) ----------------
__device__ __forceinline__ uint32_t smem_u32(const void* p) {
    uint32_t a;
    asm("{ .reg .u64 t; cvta.to.shared.u64 t, %1; cvt.u32.u64 %0, t; }" : "=r"(a) : "l"(p));
    return a;
}
__device__ __forceinline__ void ldsm_x4(uint32_t* r, uint32_t a) {
    asm volatile("ldmatrix.sync.aligned.m8n8.x4.shared.b16 {%0,%1,%2,%3}, [%4];"
        : "=r"(r[0]), "=r"(r[1]), "=r"(r[2]), "=r"(r[3]) : "r"(a));
}
__device__ __forceinline__ void ldsm_x2(uint32_t* r, uint32_t a) {
    asm volatile("ldmatrix.sync.aligned.m8n8.x2.shared.b16 {%0,%1}, [%2];"
        : "=r"(r[0]), "=r"(r[1]) : "r"(a));
}
__device__ __forceinline__ void mma_bf16(float* c, const uint32_t* a, const uint32_t* b) {
    asm volatile(
        "mma.sync.aligned.m16n8k16.row.col.f32.bf16.bf16.f32 "
        "{%0,%1,%2,%3}, {%4,%5,%6,%7}, {%8,%9}, {%0,%1,%2,%3};"
        : "+f"(c[0]), "+f"(c[1]), "+f"(c[2]), "+f"(c[3])
        : "r"(a[0]), "r"(a[1]), "r"(a[2]), "r"(a[3]), "r"(b[0]), "r"(b[1]));
}
__device__ __forceinline__ void mbar_init(uint32_t mbar, uint32_t cnt) {
    asm volatile("mbarrier.init.shared.b64 [%0], %1;" :: "r"(mbar), "r"(cnt) : "memory");
}
__device__ __forceinline__ void mbar_expect_tx(uint32_t mbar, uint32_t bytes) {
    asm volatile("mbarrier.arrive.expect_tx.shared.b64 _, [%0], %1;" :: "r"(mbar), "r"(bytes) : "memory");
}
__device__ __forceinline__ void bulk_g2s(uint32_t dst, const void* src, uint32_t bytes, uint32_t mbar) {
    asm volatile("cp.async.bulk.shared::cta.global.mbarrier::complete_tx::bytes [%0], [%1], %2, [%3];"
        :: "r"(dst), "l"(src), "r"(bytes), "r"(mbar) : "memory");
}
__device__ __forceinline__ void mbar_wait(uint32_t mbar, uint32_t parity) {
    uint32_t done;
    asm volatile(
        "{\n\t.reg .pred p;\n\t"
        "mbarrier.try_wait.parity.acquire.cta.shared::cta.b64 p, [%1], %2;\n\t"
        "selp.b32 %0, 1, 0, p;\n\t}"
        : "=r"(done) : "r"(mbar), "r"(parity) : "memory");
    if (!done) {
        asm volatile(
            "{\n\t.reg .pred P1;\n\t"
            "WAIT_LOOP_%=:\n\t"
            "mbarrier.try_wait.parity.acquire.cta.shared::cta.b64 P1, [%0], %1, 0x989680;\n\t"
            "@P1 bra.uni WAIT_DONE_%=;\n\t"
            "bra.uni WAIT_LOOP_%=;\n\t"
            "WAIT_DONE_%=:\n\t}"
            :: "r"(mbar), "r"(parity) : "memory");
    }
}
__device__ __forceinline__ void prefetch_l2(const void* p) {
    asm volatile("prefetch.global.L2 [%0];" :: "l"(p));
}
// swizzled element index within a 64-ch row, key = row&7
__device__ __forceinline__ int swz_elem(int c, int key) {
    return (((c >> 3) ^ key) << 3) + (c & 7);
}

// ---------------- input conversion (fused: grid.y = 0 -> nbr, 1 -> ref) ----------------
__global__ void convert_in_kernel(const float* __restrict__ in0, const float* __restrict__ in1,
                                  float* __restrict__ outF,
                                  __nv_bfloat16* __restrict__ hi0, __nv_bfloat16* __restrict__ lo0,
                                  __nv_bfloat16* __restrict__ hi1, __nv_bfloat16* __restrict__ lo1)
{
    int p = blockIdx.x * blockDim.x + threadIdx.x;
    if (p >= BB * HWW) return;
    const bool second = (blockIdx.y != 0);
    const float* in = second ? in1 : in0;
    __nv_bfloat16* hi = second ? hi1 : hi0;
    __nv_bfloat16* lo = second ? lo1 : lo0;
    int x = p % WW; int t = p / WW; int y = t % HH; int b = t / HH;
    size_t g = (size_t)GUARD + (size_t)b * PIMG + (size_t)(y + 1) * PW + (x + 1);
    const int key = (int)(g & 7);
#pragma unroll
    for (int c = 0; c < 64; ++c) {
        float v = in[((size_t)(b * 64 + c)) * HWW + (size_t)y * WW + x];
        if (!second) outF[g * 64 + c] = v;
        __nv_bfloat16 h = __float2bfloat16(v);
        int sc = swz_elem(c, key);
        hi[g * 64 + sc] = h;
        lo[g * 64 + sc] = __float2bfloat16(v - __bfloat162float(h));
    }
}

// ---------------- fused weight prep (pre-swizzled image) ----------------
struct WPrepArgs {
    const float* src[10];
    int O[10];
    int Cin[10];
    long woff[10];
};
__global__ void weight_prep_all_kernel(WPrepArgs a,
                                       __nv_bfloat16* __restrict__ whi,
                                       __nv_bfloat16* __restrict__ wlo)
{
    const int ci = blockIdx.y;
    const int O = a.O[ci], Cin = a.Cin[ci];
    const int n = O * Cin * 9;
    const float* __restrict__ w = a.src[ci];
    const long woff = a.woff[ci];
    for (int idx = blockIdx.x * blockDim.x + threadIdx.x; idx < n;
         idx += gridDim.x * blockDim.x) {
        int tap = idx % 9; int t = idx / 9; int cin = t % Cin; int o = t / Cin;
        float v = w[idx];
        int seg = cin >> 6, k = cin & 63;
        size_t blockb = (size_t)woff + (((size_t)tap * (Cin >> 6) + seg) * O) * 64;
        size_t dst = blockb + (size_t)o * 64 + (size_t)swz_elem(k, o & 7);
        __nv_bfloat16 h = __float2bfloat16(v);
        whi[dst] = h;
        wlo[dst] = __float2bfloat16(v - __bfloat162float(h));
    }
}

// ---------------- conv: all staging via cp.async.bulk; warp-7 L2 prefetch of next A ----------------
template<int NT, int NTOT, int SEGS, bool EPI_F32, bool EPI_BF16, bool LRELU>
__global__ __launch_bounds__(256, 2)
void conv_mma_kernel(const __nv_bfloat16* __restrict__ Ahi0, const __nv_bfloat16* __restrict__ Alo0,
                     const __nv_bfloat16* __restrict__ Ahi1, const __nv_bfloat16* __restrict__ Alo1,
                     const __nv_bfloat16* __restrict__ Whi, const __nv_bfloat16* __restrict__ Wlo,
                     const float* __restrict__ bias,
                     float* __restrict__ outF,
                     __nv_bfloat16* __restrict__ outHi, __nv_bfloat16* __restrict__ outLo)
{
    extern __shared__ __align__(1024) char smem[];
    constexpr int AROWS = 258;
    constexpr int ABUF  = AROWS * 128;
    constexpr int BBUF  = NT * 128;
    constexpr int OFF_A = 1024;
    constexpr int OFF_B = OFF_A + 2 * ABUF;
    constexpr int NB  = NT / 8;
    constexpr int NBP = NB / 2;
    constexpr bool NBODD = (NB & 1) != 0;
    constexpr int NSS = 3 * SEGS;
    constexpr int NST = 9 * SEGS;

    float* sBias = (float*)smem;                 // [0, 512)
    const uint32_t sb = smem_u32(smem);
    const uint32_t mb0 = sb + 512;
    const uint32_t mb1 = sb + 520;
    const uint32_t mbA = sb + 528;

    const int tid  = threadIdx.x;
    const int lane = tid & 31;
    const int warp = tid >> 5;
    const int ocb  = blockIdx.y;
    const long m0  = (long)blockIdx.x * 256;

    for (int i = tid; i < NT; i += 256) sBias[i] = bias[ocb * NT + i];

    float acc[2][NB][4];
#pragma unroll
    for (int mt = 0; mt < 2; ++mt)
#pragma unroll
        for (int nb = 0; nb < NB; ++nb)
#pragma unroll
            for (int j = 0; j < 4; ++j) acc[mt][nb][j] = 0.f;

    const int l7 = lane & 7;
    const uint32_t aRow = (uint32_t)(warp * 32 + ((lane >> 3) & 1) * 8 + l7);
    const int aU = (lane >> 4) & 1;
    const int bKh = (lane >> 3) & 1;
    const int bNs = (lane >> 4) & 1;

    auto panel_src = [&](int ss, const __nv_bfloat16*& ah, const __nv_bfloat16*& al, long& base) {
        const int dy  = ss / SEGS;
        const int seg = ss % SEGS;
        ah = (seg == 0) ? Ahi0 : Ahi1;
        al = (seg == 0) ? Alo0 : Alo1;
        base = (long)GUARD + m0 + (long)(dy - 1) * PW - 1;
    };
    auto bulk_A = [&](int ss) {
        const __nv_bfloat16 *ah, *al; long base;
        panel_src(ss, ah, al, base);
        mbar_expect_tx(mbA, 2 * ABUF);
        bulk_g2s(sb + OFF_A,        ah + (size_t)base * 64, ABUF, mbA);
        bulk_g2s(sb + OFF_A + ABUF, al + (size_t)base * 64, ABUF, mbA);
    };
    // warp-7-only L2 warmer: 32 lanes cover 258 lines at stride 8 (prefetch grabs 128B line)
    auto prefetch_A_w7 = [&](int ss) {
        const __nv_bfloat16 *ah, *al; long base;
        panel_src(ss, ah, al, base);
        for (int r = lane * 8; r < AROWS; r += 32 * 8) {
            prefetch_l2(ah + (size_t)(base + r) * 64);
            prefetch_l2(al + (size_t)(base + r) * 64);
        }
    };
    auto bulk_B = [&](int s) {
        const int ss = s / 3, dxi = s % 3;
        const int dy = ss / SEGS, seg = ss % SEGS;
        const int tap = dy * 3 + dxi;
        const size_t wbase = (((size_t)tap * SEGS + seg) * NTOT + (size_t)ocb * NT) * 64;
        const uint32_t mb = (s & 1) ? mb1 : mb0;
        const uint32_t dBH = sb + OFF_B + (s & 1) * 2 * BBUF;
        mbar_expect_tx(mb, 2 * BBUF);
        bulk_g2s(dBH,        Whi + wbase, BBUF, mb);
        bulk_g2s(dBH + BBUF, Wlo + wbase, BBUF, mb);
    };

    if (tid == 0) { mbar_init(mb0, 1); mbar_init(mb1, 1); mbar_init(mbA, 1); }
    __syncthreads();
    if (tid == 0) { bulk_A(0); bulk_B(0); }

    for (int s = 0; s < NST; ++s) {
        const int ss = s / 3, dxi = s % 3;

        if (dxi == 0) mbar_wait(mbA, ss & 1);            // A panel for this superstage
        mbar_wait((s & 1) ? mb1 : mb0, (s >> 1) & 1);    // B(s)
        __syncthreads();                                 // all warps past compute(s-1)

        if (tid == 0 && s + 1 < NST) bulk_B(s + 1);
        if (warp == 7 && dxi == 1 && ss + 1 < NSS) prefetch_A_w7(ss + 1);

        const int dy = ss / SEGS;
        const int bm = (int)(((dy - 1) * PW - 1) & 7);   // (base&7); m0,GUARD ≡ 0 mod 8
        const uint32_t aH = sb + OFF_A;
        const uint32_t aL = aH + ABUF;
        const uint32_t bH = sb + OFF_B + (s & 1) * 2 * BBUF;
        const uint32_t bL = bH + BBUF;
        const uint32_t krow = (uint32_t)((l7 + dxi + bm) & 7);

#pragma unroll
        for (int c = 0; c < 4; ++c) {
            uint32_t ahf[2][4], alf[2][4];
#pragma unroll
            for (int mt = 0; mt < 2; ++mt) {
                uint32_t row = aRow + mt * 16 + dxi;
                uint32_t off = row * 128 + ((uint32_t)((2 * c + aU)) ^ krow) * 16;
                ldsm_x4(ahf[mt], aH + off);
                ldsm_x4(alf[mt], aL + off);
            }
#pragma unroll
            for (int nbp = 0; nbp < NBP; ++nbp) {
                uint32_t row = (uint32_t)((nbp * 2 + bNs) * 8 + l7);
                uint32_t offb = row * 128 + ((uint32_t)((2 * c + bKh) ^ l7)) * 16;
                uint32_t bh[4], bl[4];
                ldsm_x4(bh, bH + offb);
                ldsm_x4(bl, bL + offb);
#pragma unroll
                for (int half = 0; half < 2; ++half) {
                    const int nb = nbp * 2 + half;
                    mma_bf16(acc[0][nb], ahf[0], bh + 2 * half);
                    mma_bf16(acc[1][nb], ahf[1], bh + 2 * half);
                    mma_bf16(acc[0][nb], ahf[0], bl + 2 * half);
                    mma_bf16(acc[1][nb], ahf[1], bl + 2 * half);
                    mma_bf16(acc[0][nb], alf[0], bh + 2 * half);
                    mma_bf16(acc[1][nb], alf[1], bh + 2 * half);
                }
            }
            if (NBODD) {
                const int nb = NB - 1;
                uint32_t row = (uint32_t)(nb * 8 + l7);
                uint32_t offb = row * 128 + ((uint32_t)((2 * c + bKh) ^ l7)) * 16;
                uint32_t bh[2], bl[2];
                ldsm_x2(bh, bH + offb);
                ldsm_x2(bl, bL + offb);
                mma_bf16(acc[0][nb], ahf[0], bh);
                mma_bf16(acc[1][nb], ahf[1], bh);
                mma_bf16(acc[0][nb], ahf[0], bl);
                mma_bf16(acc[1][nb], ahf[1], bl);
                mma_bf16(acc[0][nb], alf[0], bh);
                mma_bf16(acc[1][nb], alf[1], bh);
            }
        }

        if (dxi == 2 && ss + 1 < NSS) {
            __syncthreads();          // all warps done reading A(ss)
            if (tid == 0) bulk_A(ss + 1);
        }
    }

    // ---- epilogue (bf16 outputs written SWIZZLED) ----
    const long gbase = m0 + warp * 32;
    const int ncol0 = 2 * (lane & 3);
#pragma unroll
    for (int mt = 0; mt < 2; ++mt) {
#pragma unroll
        for (int half = 0; half < 2; ++half) {
            long g = gbase + mt * 16 + (lane >> 2) + half * 8;
            bool valid = (g < MROWS);
            if (valid) {
                long q = g % PIMG;
                int py = (int)(q / PW), px = (int)(q % PW);
                valid = (py >= 1) && (py < PW - 1) && (px >= 1) && (px < PW - 1);
            }
            if (!valid) continue;
            const size_t orow = (size_t)(GUARD + g);
            const int okey = (int)(orow & 7);
#pragma unroll
            for (int nb = 0; nb < NB; ++nb) {
                float v0 = acc[mt][nb][half * 2 + 0] + sBias[nb * 8 + ncol0];
                float v1 = acc[mt][nb][half * 2 + 1] + sBias[nb * 8 + ncol0 + 1];
                if (LRELU) {
                    v0 = (v0 >= 0.f) ? v0 : 0.1f * v0;
                    v1 = (v1 >= 0.f) ? v1 : 0.1f * v1;
                }
                const int col = ocb * NT + nb * 8 + ncol0;
                if (EPI_F32) {
                    outF[orow * NTOT + col]     = v0;
                    outF[orow * NTOT + col + 1] = v1;
                }
                if (EPI_BF16) {
                    int sc = swz_elem(col, okey);
                    __nv_bfloat16 h0 = __float2bfloat16(v0);
                    __nv_bfloat16 h1 = __float2bfloat16(v1);
                    outHi[orow * NTOT + sc]     = h0;
                    outHi[orow * NTOT + sc + 1] = h1;
                    outLo[orow * NTOT + sc]     = __float2bfloat16(v0 - __bfloat162float(h0));
                    outLo[orow * NTOT + sc + 1] = __float2bfloat16(v1 - __bfloat162float(h1));
                }
            }
        }
    }
}

// ---------------- DCNv2 via MMA (M=128, 2 threads/pixel x 4 dg; bulk-B) ----------------
template<bool LRELU, bool NCHW_OUT>
__global__ __launch_bounds__(256, 2)
void dcn_mma_kernel(const float* __restrict__ xf,
                    const float* __restrict__ off,
                    const __nv_bfloat16* __restrict__ Whi, const __nv_bfloat16* __restrict__ Wlo,
                    const float* __restrict__ bias,
                    float* __restrict__ outF,
                    __nv_bfloat16* __restrict__ outHi, __nv_bfloat16* __restrict__ outLo)
{
    extern __shared__ __align__(1024) char smem[];
    constexpr int ABUF  = 128 * 128;
    constexpr int BBUF  = 64 * 128;
    constexpr int OFF_A = 1024;
    constexpr int OFF_B = OFF_A + 2 * ABUF;

    float* sBias = (float*)smem;
    const uint32_t sb = smem_u32(smem);
    const uint32_t mb0 = sb + 512;
    const uint32_t mb1 = sb + 520;

    const int tid  = threadIdx.x;
    const int lane = tid & 31;
    const int warp = tid >> 5;
    const long m0  = (long)blockIdx.x * 128;

    if (tid < 64) sBias[tid] = bias[tid];

    const int p   = tid >> 1;
    const int dg0 = (tid & 1) * 4;
    const long g  = m0 + p;
    const long gcl = (g < MROWS) ? g : 0;
    const int b   = (int)(gcl / PIMG);
    const long q  = gcl % PIMG;
    const int gy  = (int)(q / PW) - 1;
    const int gx  = (int)(q % PW) - 1;
    const size_t prow = (size_t)GUARD + gcl;
    const float* offP = off + prow * 216;
    const float* xfb  = xf + ((size_t)GUARD + (size_t)b * PIMG) * 64;

    float acc[8][4];
#pragma unroll
    for (int nb = 0; nb < 8; ++nb)
#pragma unroll
        for (int j = 0; j < 4; ++j) acc[nb][j] = 0.f;

    const int l7 = lane & 7;
    const uint32_t aRow = (uint32_t)(warp * 16 + ((lane >> 3) & 1) * 8 + l7);
    const int aU = (lane >> 4) & 1;
    const int bKh = (lane >> 3) & 1;
    const int bNs = (lane >> 4) & 1;

    auto bulk_B = [&](int s) {
        const size_t wbase = (size_t)s * 64 * 64;
        const uint32_t mb = (s & 1) ? mb1 : mb0;
        const uint32_t dBH = sb + OFF_B + (s & 1) * 2 * BBUF;
        mbar_expect_tx(mb, 2 * BBUF);
        bulk_g2s(dBH,        Whi + wbase, BBUF, mb);
        bulk_g2s(dBH + BBUF, Wlo + wbase, BBUF, mb);
    };

    if (tid == 0) { mbar_init(mb0, 1); mbar_init(mb1, 1); }
    __syncthreads();
    if (tid == 0) bulk_B(0);

    for (int s = 0; s < 9; ++s) {
        __syncthreads();
        if (tid == 0 && s + 1 < 9) bulk_B(s + 1);

        const int ky = s / 3, kx = s % 3;
        const uint32_t arow_sw = (uint32_t)p * 128;
        const uint32_t asx = ((uint32_t)p & 7) * 16;
#pragma unroll
        for (int d = 0; d < 4; ++d) {
            const int dg = dg0 + d;
            float dy = offP[dg * 18 + 2 * s + 0];
            float dx = offP[dg * 18 + 2 * s + 1];
            float ml = offP[144 + dg * 9 + s];
            float m  = 1.f / (1.f + __expf(-ml));

            float py = (float)gy - 1.f + (float)ky + dy;
            float px = (float)gx - 1.f + (float)kx + dx;
            float y0f = floorf(py), x0f = floorf(px);
            float wy = py - y0f, wx = px - x0f;
            int y0 = (int)y0f, x0 = (int)x0f;

            float cw00 = (1.f - wy) * (1.f - wx);
            float cw01 = (1.f - wy) * wx;
            float cw10 = wy * (1.f - wx);
            float cw11 = wy * wx;

            float sv[8];
#pragma unroll
            for (int i = 0; i < 8; ++i) sv[i] = 0.f;
#pragma unroll
            for (int cy = 0; cy < 2; ++cy) {
#pragma unroll
                for (int cx = 0; cx < 2; ++cx) {
                    int yy = y0 + cy, xx = x0 + cx;
                    float cwv = (cy == 0) ? ((cx == 0) ? cw00 : cw01)
                                          : ((cx == 0) ? cw10 : cw11);
                    if (yy >= 0 && yy < HH && xx >= 0 && xx < WW) {
                        const float4* ptr = reinterpret_cast<const float4*>(
                            xfb + ((size_t)(yy + 1) * PW + (xx + 1)) * 64 + dg * 8);
                        float4 a = __ldg(&ptr[0]);
                        float4 c = __ldg(&ptr[1]);
                        sv[0] += cwv * a.x; sv[1] += cwv * a.y;
                        sv[2] += cwv * a.z; sv[3] += cwv * a.w;
                        sv[4] += cwv * c.x; sv[5] += cwv * c.y;
                        sv[6] += cwv * c.z; sv[7] += cwv * c.w;
                    }
                }
            }
            uint32_t hp[4], lp[4];
#pragma unroll
            for (int i = 0; i < 4; ++i) {
                float v0 = sv[2 * i] * m, v1 = sv[2 * i + 1] * m;
                __nv_bfloat16 h0 = __float2bfloat16(v0);
                __nv_bfloat16 h1 = __float2bfloat16(v1);
                __nv_bfloat16 e0 = __float2bfloat16(v0 - __bfloat162float(h0));
                __nv_bfloat16 e1 = __float2bfloat16(v1 - __bfloat162float(h1));
                hp[i] = ((uint32_t)*(uint16_t*)&h1 << 16) | (uint32_t)*(uint16_t*)&h0;
                lp[i] = ((uint32_t)*(uint16_t*)&e1 << 16) | (uint32_t)*(uint16_t*)&e0;
            }
            uint32_t o = arow_sw + (((uint32_t)dg * 16) ^ asx);
            *(uint4*)(smem + OFF_A + o)        = make_uint4(hp[0], hp[1], hp[2], hp[3]);
            *(uint4*)(smem + OFF_A + ABUF + o) = make_uint4(lp[0], lp[1], lp[2], lp[3]);
        }

        mbar_wait((s & 1) ? mb1 : mb0, (s >> 1) & 1);
        __syncthreads();

        const uint32_t aH = sb + OFF_A;
        const uint32_t aL = aH + ABUF;
        const uint32_t bH = sb + OFF_B + (s & 1) * 2 * BBUF;
        const uint32_t bL = bH + BBUF;

#pragma unroll
        for (int c = 0; c < 4; ++c) {
            uint32_t ahf[4], alf[4];
            uint32_t offA = aRow * 128 + ((uint32_t)((2 * c + aU) ^ l7)) * 16;
            ldsm_x4(ahf, aH + offA);
            ldsm_x4(alf, aL + offA);
#pragma unroll
            for (int nbp = 0; nbp < 4; ++nbp) {
                uint32_t row = (uint32_t)((nbp * 2 + bNs) * 8 + l7);
                uint32_t offb2 = row * 128 + ((uint32_t)((2 * c + bKh) ^ l7)) * 16;
                uint32_t bh[4], bl[4];
                ldsm_x4(bh, bH + offb2);
                ldsm_x4(bl, bL + offb2);
#pragma unroll
                for (int half = 0; half < 2; ++half) {
                    const int nb = nbp * 2 + half;
                    mma_bf16(acc[nb], ahf, bh + 2 * half);
                    mma_bf16(acc[nb], ahf, bl + 2 * half);
                    mma_bf16(acc[nb], alf, bh + 2 * half);
                }
            }
        }
    }

    const long gbase = m0 + warp * 16;
    const int ncol0 = 2 * (lane & 3);
#pragma unroll
    for (int half = 0; half < 2; ++half) {
        long g2 = gbase + (lane >> 2) + half * 8;
        bool valid = (g2 < MROWS);
        int b2 = 0, gy2 = 0, gx2 = 0;
        if (valid) {
            b2 = (int)(g2 / PIMG);
            long q2 = g2 % PIMG;
            gy2 = (int)(q2 / PW) - 1;
            gx2 = (int)(q2 % PW) - 1;
            valid = (gy2 >= 0) && (gy2 < HH) && (gx2 >= 0) && (gx2 < WW);
        }
        if (!valid) continue;
        const size_t orow = (size_t)(GUARD + g2);
        const int okey = (int)(orow & 7);
#pragma unroll
        for (int nb = 0; nb < 8; ++nb) {
#pragma unroll
            for (int j = 0; j < 2; ++j) {
                const int oc = nb * 8 + ncol0 + j;
                float v = acc[nb][half * 2 + j] + sBias[oc];
                if (LRELU) v = (v >= 0.f) ? v : 0.1f * v;
                if (NCHW_OUT) {
                    outF[((size_t)(b2 * CC + oc)) * HWW + (size_t)gy2 * WW + gx2] = v;
                } else {
                    int sc = swz_elem(oc, okey);
                    __nv_bfloat16 h = __float2bfloat16(v);
                    outHi[orow * 64 + sc] = h;
                    outLo[orow * 64 + sc] = __float2bfloat16(v - __bfloat162float(h));
                }
            }
        }
    }
}

// ---------------- launch ----------------
extern "C" void kernel_launch(void* const* d_in, const int* in_sizes, int n_in,
                              void* d_out, int out_size)
{
    const float* nbr     = (const float*)d_in[0];
    const float* ref     = (const float*)d_in[1];
    const float* oc1_w   = (const float*)d_in[2];
    const float* oc1_b   = (const float*)d_in[3];
    const float* oc2_w   = (const float*)d_in[4];
    const float* oc2_b   = (const float*)d_in[5];
    const float* d1off_w = (const float*)d_in[6];
    const float* d1off_b = (const float*)d_in[7];
    const float* dcn1_w  = (const float*)d_in[8];
    const float* dcn1_b  = (const float*)d_in[9];
    const float* fc_w    = (const float*)d_in[10];
    const float* fc_b    = (const float*)d_in[11];
    const float* cas1_w  = (const float*)d_in[12];
    const float* cas1_b  = (const float*)d_in[13];
    const float* cas2_w  = (const float*)d_in[14];
    const float* cas2_b  = (const float*)d_in[15];
    const float* cdoff_w = (const float*)d_in[16];
    const float* cdoff_b = (const float*)d_in[17];
    const float* casd_w  = (const float*)d_in[18];
    const float* casd_b  = (const float*)d_in[19];
    float* outp = (float*)d_out;

    float *xnbr, *xfc, *offb;
    __nv_bfloat16 *nh, *nl, *rh, *rl, *b1h, *b1l, *b2h, *b2l, *b3h, *b3l, *b4h, *b4l, *wh, *wl;
    cudaGetSymbolAddress((void**)&xnbr, g_xnbr);
    cudaGetSymbolAddress((void**)&xfc,  g_xfc);
    cudaGetSymbolAddress((void**)&offb, g_offb);
    cudaGetSymbolAddress((void**)&nh,  g_nbr_h); cudaGetSymbolAddress((void**)&nl, g_nbr_l);
    cudaGetSymbolAddress((void**)&rh,  g_ref_h); cudaGetSymbolAddress((void**)&rl, g_ref_l);
    cudaGetSymbolAddress((void**)&b1h, g_b1_h);  cudaGetSymbolAddress((void**)&b1l, g_b1_l);
    cudaGetSymbolAddress((void**)&b2h, g_b2_h);  cudaGetSymbolAddress((void**)&b2l, g_b2_l);
    cudaGetSymbolAddress((void**)&b3h, g_b3_h);  cudaGetSymbolAddress((void**)&b3l, g_b3_l);
    cudaGetSymbolAddress((void**)&b4h, g_b4_h);  cudaGetSymbolAddress((void**)&b4l, g_b4_l);
    cudaGetSymbolAddress((void**)&wh,  g_w_h);   cudaGetSymbolAddress((void**)&wl,  g_w_l);

    auto C64S2 = conv_mma_kernel<64, 64, 2, false, true,  true >;
    auto C64S1 = conv_mma_kernel<64, 64, 1, false, true,  true >;
    auto C216  = conv_mma_kernel<72, 216, 1, true,  false, false>;
    auto CFC   = conv_mma_kernel<64, 64, 1, true,  true,  false>;
    auto DCN1  = dcn_mma_kernel<false, false>;
    auto DCNC  = dcn_mma_kernel<true,  true >;

    const int smem64 = 1024 + 2 * (258 * 128) + 4 * 64 * 128;   // 99840
    const int smem72 = 1024 + 2 * (258 * 128) + 4 * 72 * 128;   // 103936
    const int smemD  = 1024 + 2 * (128 * 128) + 4 * 64 * 128;   // 66560
    cudaFuncSetAttribute(C64S2, cudaFuncAttributeMaxDynamicSharedMemorySize, smem64);
    cudaFuncSetAttribute(C64S1, cudaFuncAttributeMaxDynamicSharedMemorySize, smem64);
    cudaFuncSetAttribute(CFC,   cudaFuncAttributeMaxDynamicSharedMemorySize, smem64);
    cudaFuncSetAttribute(C216,  cudaFuncAttributeMaxDynamicSharedMemorySize, smem72);
    cudaFuncSetAttribute(DCN1,  cudaFuncAttributeMaxDynamicSharedMemorySize, smemD);
    cudaFuncSetAttribute(DCNC,  cudaFuncAttributeMaxDynamicSharedMemorySize, smemD);

    const int cvtGrid = (BB * HWW + 255) / 256;
    dim3 gCvt(cvtGrid, 2);
    dim3 g64(NTIL256, 1), g216(NTIL256, 3);

    convert_in_kernel<<<gCvt, 256>>>(nbr, ref, xnbr, nh, nl, rh, rl);
    {
        WPrepArgs a;
        a.src[0] = oc1_w;   a.O[0] = 64;  a.Cin[0] = 128; a.woff[0] = WOFF_OC1;
        a.src[1] = oc2_w;   a.O[1] = 64;  a.Cin[1] = 64;  a.woff[1] = WOFF_OC2;
        a.src[2] = d1off_w; a.O[2] = 216; a.Cin[2] = 64;  a.woff[2] = WOFF_D1OFF;
        a.src[3] = fc_w;    a.O[3] = 64;  a.Cin[3] = 64;  a.woff[3] = WOFF_FC;
        a.src[4] = cas1_w;  a.O[4] = 64;  a.Cin[4] = 128; a.woff[4] = WOFF_CAS1;
        a.src[5] = cas2_w;  a.O[5] = 64;  a.Cin[5] = 64;  a.woff[5] = WOFF_CAS2;
        a.src[6] = cdoff_w; a.O[6] = 216; a.Cin[6] = 64;  a.woff[6] = WOFF_CDOFF;
        a.src[7] = dcn1_w;  a.O[7] = 64;  a.Cin[7] = 64;  a.woff[7] = WOFF_DCN1;
        a.src[8] = casd_w;  a.O[8] = 64;  a.Cin[8] = 64;  a.woff[8] = WOFF_CASD;
        a.src[9] = casd_w;  a.O[9] = 0;   a.Cin[9] = 64;  a.woff[9] = WOFF_CASD;
        dim3 gW(64, 10);
        weight_prep_all_kernel<<<gW, 256>>>(a, wh, wl);
    }

    C64S2<<<g64, 256, smem64>>>(nh, nl, rh, rl, wh + WOFF_OC1, wl + WOFF_OC1, oc1_b, nullptr, b1h, b1l);
    C64S1<<<g64, 256, smem64>>>(b1h, b1l, nullptr, nullptr, wh + WOFF_OC2, wl + WOFF_OC2, oc2_b, nullptr, b2h, b2l);
    C216<<<g216, 256, smem72>>>(b2h, b2l, nullptr, nullptr, wh + WOFF_D1OFF, wl + WOFF_D1OFF, d1off_b, offb, nullptr, nullptr);
    DCN1<<<NTIL128, 256, smemD>>>(xnbr, offb, wh + WOFF_DCN1, wl + WOFF_DCN1, dcn1_b, nullptr, b3h, b3l);
    CFC<<<g64, 256, smem64>>>(b3h, b3l, nullptr, nullptr, wh + WOFF_FC, wl + WOFF_FC, fc_b, xfc, b4h, b4l);
    C64S2<<<g64, 256, smem64>>>(b4h, b4l, rh, rl, wh + WOFF_CAS1, wl + WOFF_CAS1, cas1_b, nullptr, b1h, b1l);
    C64S1<<<g64, 256, smem64>>>(b1h, b1l, nullptr, nullptr, wh + WOFF_CAS2, wl + WOFF_CAS2, cas2_b, nullptr, b2h, b2l);
    C216<<<g216, 256, smem72>>>(b2h, b2l, nullptr, nullptr, wh + WOFF_CDOFF, wl + WOFF_CDOFF, cdoff_b, offb, nullptr, nullptr);
    DCNC<<<NTIL128, 256, smemD>>>(xfc, offb, wh + WOFF_CASD, wl + WOFF_CASD, casd_b, outp, nullptr, nullptr);

    (void)in_sizes; (void)n_in; (void)out_size;
}